// round 14
// baseline (speedup 1.0000x reference)
#include <cuda_runtime.h>
#include <cuda_fp16.h>

#define NN 100000
#define MM 32
#define DD 3
#define BB 8

// fs transposed to [n][d][b] fp16: row n = 8 uint2 slots (64 B, aligned).
// uint4 view: slot s = dim s, batches 0-7; slot 3 = explicit zeros.
__device__ __align__(128) uint2 g_fsth[NN * 8];

// 1 if stencil buffer is int64, 0 if int32 (jax x64-disabled downgrade).
__device__ int g_idx_is64;

// ---------------------------------------------------------------------------
// Kernel 1: transpose+compress fs (B,N,D) f32 -> [n][d][b] fp16 rows.
// Thread 0 also detects idx dtype. d==0 thread zeroes pad slots 6,7.
// ---------------------------------------------------------------------------
__global__ void __launch_bounds__(256) transpose_fs_kernel(
    const float* __restrict__ fs, const int* __restrict__ idx32)
{
    int t = blockIdx.x * 256 + threadIdx.x;   // t = n*3 + d
    if (t == 0) {
        int all_zero = 1;
#pragma unroll
        for (int k = 0; k < 64; k++)
            if (idx32[2 * k + 1] != 0) { all_zero = 0; break; }
        g_idx_is64 = all_zero;
    }
    if (t >= NN * DD) return;
    float v[BB];
#pragma unroll
    for (int b = 0; b < BB; b++) v[b] = __ldg(fs + (size_t)b * (NN * DD) + t);
    int n = t / DD;
    int d = t - n * DD;

    __half2 a01 = __floats2half2_rn(v[0], v[1]);
    __half2 a23 = __floats2half2_rn(v[2], v[3]);
    __half2 a45 = __floats2half2_rn(v[4], v[5]);
    __half2 a67 = __floats2half2_rn(v[6], v[7]);
    uint2 u0, u1;
    u0.x = *reinterpret_cast<unsigned int*>(&a01);
    u0.y = *reinterpret_cast<unsigned int*>(&a23);
    u1.x = *reinterpret_cast<unsigned int*>(&a45);
    u1.y = *reinterpret_cast<unsigned int*>(&a67);
    g_fsth[(size_t)n * 8 + d * 2]     = u0;   // d, batches 0-3
    g_fsth[(size_t)n * 8 + d * 2 + 1] = u1;   // d, batches 4-7
    if (d == 0) {
        uint2 z = make_uint2(0u, 0u);
        g_fsth[(size_t)n * 8 + 6] = z;        // zero pad (lane j2==3 reads this)
        g_fsth[(size_t)n * 8 + 7] = z;
    }
}

// ---------------------------------------------------------------------------
// Kernel 2: gather + contraction.
// Block = 128 threads = 32 nodes (4 lanes/node, 8 nodes/warp).
// Lane j2 owns dim d=j2 for its node, all 8 batches (j2==3 rides zeros).
// Per m: one LDG.128 covers 8 nodes' rows (L=8, best LSU cost/row);
// fp16 weights + idx staged in smem; width-4 butterfly epilogue.
// ---------------------------------------------------------------------------
#define PI3  36    // s_idx ints per node (36 mod 32 = 4)
#define PDH3 36    // s_wh halves per d-row  (72 B -> 8B-aligned)
#define PNH3 112   // s_wh halves per node   (224 B, 8B-aligned)
#define PO3  36    // s_out floats per batch row (32 + 4)

__global__ void __launch_bounds__(128, 16) rbffd_main_kernel(
    const float* __restrict__ w,        // (N, D, M) f32
    const int* __restrict__ idx32,      // (N, M) int32 or int64 pairs
    float* __restrict__ out)            // (B, N) f32
{
    const unsigned FULL = 0xffffffffu;
    __shared__ __align__(16) __half s_wh[32 * PNH3];  // 7168 B
    __shared__ __align__(16) int    s_idx[32 * PI3];  // 4608 B
    __shared__ float s_out[BB * PO3];                 // 1152 B

    const int node0 = blockIdx.x * 32;
    const int nodeL = threadIdx.x >> 2;               // 0..31 local node
    const int j2    = threadIdx.x & 3;                // lane in node group = d

    // --- stage stencil indices: 256 int4, 2 per thread, clamped ---
#pragma unroll
    for (int p = 0; p < 2; p++) {
        int q  = threadIdx.x + p * 128;               // int4 slot 0..255
        int nl = q >> 3;                              // local node
        int g  = q & 7;                               // int4 within node
        int4 ci;
        if (g_idx_is64) {
            const int* irow = idx32 + (size_t)(node0 + nl) * (MM * 2);
            int4 lo = __ldg((const int4*)(irow + 8 * g));
            int4 hi = __ldg((const int4*)(irow + 8 * g + 4));
            ci = make_int4(lo.x, lo.z, hi.x, hi.z);   // even words = low halves
        } else {
            ci = __ldg((const int4*)(idx32 + (size_t)(node0 + nl) * MM) + g);
        }
        ci.x = ((unsigned)ci.x < (unsigned)NN) ? ci.x : 0;
        ci.y = ((unsigned)ci.y < (unsigned)NN) ? ci.y : 0;
        ci.z = ((unsigned)ci.z < (unsigned)NN) ? ci.z : 0;
        ci.w = ((unsigned)ci.w < (unsigned)NN) ? ci.w : 0;
        *(int4*)(s_idx + nl * PI3 + 4 * g) = ci;
    }

    // --- stage weights fp32 -> fp16 smem [nl][d][m]: 768 float4, 6/thread ---
    {
        const float4* wsrc = (const float4*)(w + (size_t)node0 * (DD * MM));
#pragma unroll
        for (int p = 0; p < 6; p++) {
            int q  = threadIdx.x + p * 128;           // float4 slot 0..767
            int nl = q / 24;
            int r  = q - nl * 24;                     // d*8 + m4
            int dq = r >> 3;
            int m4 = r & 7;
            float4 v = __ldg(wsrc + q);
            __half2 hA = __floats2half2_rn(v.x, v.y);
            __half2 hB = __floats2half2_rn(v.z, v.w);
            uint2 u;
            u.x = *reinterpret_cast<unsigned int*>(&hA);
            u.y = *reinterpret_cast<unsigned int*>(&hB);
            *(uint2*)(s_wh + nl * PNH3 + dq * PDH3 + m4 * 4) = u;
        }
    }

    __syncthreads();

    const int dj = (j2 < 3) ? j2 : 2;                 // lane 3: any valid row
    const __half* wl = s_wh + nodeL * PNH3 + dj * PDH3;
    const int*    il = s_idx + nodeL * PI3;
    const uint4*  fb = (const uint4*)g_fsth + j2;     // + ridx*4 per gather

    float a[8];
#pragma unroll
    for (int c = 0; c < 8; c++) a[c] = 0.f;

#pragma unroll
    for (int mo = 0; mo < 8; mo++) {
        int4 i4 = *(const int4*)(il + 4 * mo);        // idx for m=4mo..4mo+3
        uint2 wp = *(const uint2*)(wl + 4 * mo);      // 4 fp16 weights (8B aligned)
        float2 w01 = __half22float2(*reinterpret_cast<__half2*>(&wp.x));
        float2 w23 = __half22float2(*reinterpret_cast<__half2*>(&wp.y));

#pragma unroll
        for (int mi = 0; mi < 4; mi++) {
            int   ridx = (mi == 0) ? i4.x : (mi == 1) ? i4.y : (mi == 2) ? i4.z : i4.w;
            float wm   = (mi == 0) ? w01.x : (mi == 1) ? w01.y : (mi == 2) ? w23.x : w23.y;
            uint4 p = __ldg(fb + (size_t)ridx * 4);   // 16B: d=j2, batches 0-7
            float2 f0 = __half22float2(*reinterpret_cast<__half2*>(&p.x));
            float2 f1 = __half22float2(*reinterpret_cast<__half2*>(&p.y));
            float2 f2 = __half22float2(*reinterpret_cast<__half2*>(&p.z));
            float2 f3 = __half22float2(*reinterpret_cast<__half2*>(&p.w));
            a[0] += wm * f0.x;  a[1] += wm * f0.y;
            a[2] += wm * f1.x;  a[3] += wm * f1.y;
            a[4] += wm * f2.x;  a[5] += wm * f2.y;
            a[6] += wm * f3.x;  a[7] += wm * f3.y;
        }
    }

    // --- reduce over d: width-4 butterfly (lane 3 carries exact zeros) ---
#pragma unroll
    for (int c = 0; c < 8; c++) {
        a[c] += __shfl_xor_sync(FULL, a[c], 1, 4);
        a[c] += __shfl_xor_sync(FULL, a[c], 2, 4);
    }
    if (j2 == 0) {
#pragma unroll
        for (int c = 0; c < 8; c++)
            s_out[c * PO3 + nodeL] = a[c];
    }

    __syncthreads();

    // --- coalesced output: 256 values, 2 per thread ---
#pragma unroll
    for (int p = 0; p < 2; p++) {
        int q  = threadIdx.x + p * 128;               // 0..255
        int b  = q >> 5;                              // batch
        int n2 = q & 31;                              // local node
        out[(size_t)b * NN + node0 + n2] = s_out[b * PO3 + n2];
    }
}

// ---------------------------------------------------------------------------
// Launch. Inputs resolved BY SIZE (element counts distinct):
//   fs = 2,400,000   weights = 9,600,000   idx = 3,200,000
// ---------------------------------------------------------------------------
extern "C" void kernel_launch(void* const* d_in, const int* in_sizes, int n_in,
                              void* d_out, int out_size) {
    const float* fs  = nullptr;
    const float* w   = nullptr;
    const int*   idx = nullptr;

    for (int i = 0; i < n_in; i++) {
        if (in_sizes[i] == BB * NN * DD)      fs  = (const float*)d_in[i];
        else if (in_sizes[i] == NN * DD * MM) w   = (const float*)d_in[i];
        else if (in_sizes[i] == NN * MM)      idx = (const int*)d_in[i];
    }
    if (!fs)  fs  = (const float*)d_in[0];
    if (!w)   w   = (const float*)d_in[1];
    if (!idx) idx = (const int*)d_in[2];

    float* out = (float*)d_out;

    int t_threads = NN * DD;
    transpose_fs_kernel<<<(t_threads + 255) / 256, 256>>>(fs, idx);

    rbffd_main_kernel<<<NN / 32, 128>>>(w, idx, out);   // 3125 blocks
}

// round 15
// speedup vs baseline: 1.2975x; 1.2975x over previous
#include <cuda_runtime.h>
#include <cuda_fp16.h>

#define NN 100000
#define MM 32
#define DD 3
#define BB 8

// fs transposed to [n][d][b] fp16: row n = 16 words (64 B, aligned).
// word w: d = w>>2, batches (2(w&3), 2(w&3)+1); words 12-15 = explicit zeros.
__device__ __align__(128) uint2 g_fsth[NN * 8];

// 1 if stencil buffer is int64, 0 if int32 (jax x64-disabled downgrade).
__device__ int g_idx_is64;

// ---------------------------------------------------------------------------
// Kernel 1: transpose+compress fs (B,N,D) f32 -> [n][d][b] fp16 rows.
// Word layout within (n,d): 4 words = batches (0,1)(2,3)(4,5)(6,7).
// Thread 0 also detects idx dtype. d==0 thread zeroes pad words 12-15.
// ---------------------------------------------------------------------------
__global__ void __launch_bounds__(256) transpose_fs_kernel(
    const float* __restrict__ fs, const int* __restrict__ idx32)
{
    int t = blockIdx.x * 256 + threadIdx.x;   // t = n*3 + d
    if (t == 0) {
        int all_zero = 1;
#pragma unroll
        for (int k = 0; k < 64; k++)
            if (idx32[2 * k + 1] != 0) { all_zero = 0; break; }
        g_idx_is64 = all_zero;
    }
    if (t >= NN * DD) return;
    float v[BB];
#pragma unroll
    for (int b = 0; b < BB; b++) v[b] = __ldg(fs + (size_t)b * (NN * DD) + t);
    int n = t / DD;
    int d = t - n * DD;

    __half2 a01 = __floats2half2_rn(v[0], v[1]);
    __half2 a23 = __floats2half2_rn(v[2], v[3]);
    __half2 a45 = __floats2half2_rn(v[4], v[5]);
    __half2 a67 = __floats2half2_rn(v[6], v[7]);
    uint2 u0, u1;
    u0.x = *reinterpret_cast<unsigned int*>(&a01);
    u0.y = *reinterpret_cast<unsigned int*>(&a23);
    u1.x = *reinterpret_cast<unsigned int*>(&a45);
    u1.y = *reinterpret_cast<unsigned int*>(&a67);
    g_fsth[(size_t)n * 8 + d * 2]     = u0;   // d, words 0-1: batches 0-3
    g_fsth[(size_t)n * 8 + d * 2 + 1] = u1;   // d, words 2-3: batches 4-7
    if (d == 0) {
        uint2 z = make_uint2(0u, 0u);
        g_fsth[(size_t)n * 8 + 6] = z;        // zero pad: words 12-15 (d=3 lanes)
        g_fsth[(size_t)n * 8 + 7] = z;
    }
}

// ---------------------------------------------------------------------------
// Kernel 2: gather + contraction. L=2 gather shape.
// Block = 256 threads = 16 nodes (16 lanes/node, 2 nodes/warp).
// Lane l (<16): d = l>>2 (d=3 rides zero pads), batch-pair = l&3.
// Per m: one LDG.32 covers 2 nodes' rows (2 lines/instr -> 3.07 cyc,
// 1.54 cyc/row, 1 reg per in-flight load = max MLP).
// idx + fp32 weights in bank-padded smem; width-16 butterfly over d.
// ---------------------------------------------------------------------------
#define PI4 36    // s_idx ints per node   (36 mod 32 = 4)
#define PD4 36    // s_w floats per d-row  (36 mod 32 = 4)
#define PN4 116   // s_w floats per node   (3*36 + 8)
#define PO4 20    // s_out floats per batch row (16 + 4)

__global__ void __launch_bounds__(256, 8) rbffd_main_kernel(
    const float* __restrict__ w,        // (N, D, M) f32
    const int* __restrict__ idx32,      // (N, M) int32 or int64 pairs
    float* __restrict__ out)            // (B, N) f32
{
    const unsigned FULL = 0xffffffffu;
    __shared__ __align__(16) float s_w[16 * PN4];     // 7424 B
    __shared__ __align__(16) int   s_idx[16 * PI4];   // 2304 B
    __shared__ float s_out[BB * PO4];                 //  640 B

    const int node0 = blockIdx.x * 16;
    const int lane  = threadIdx.x & 31;
    const int nodeL = (threadIdx.x >> 5) * 2 + (lane >> 4);  // 0..15
    const int l     = lane & 15;                             // lane in node

    // --- stage stencil indices: 512 ints, 2 per thread, clamped ---
    {
        const int stride = g_idx_is64 ? 2 : 1;
#pragma unroll
        for (int p = 0; p < 2; p++) {
            int q  = threadIdx.x + p * 256;           // 0..511
            int nl = q >> 5;
            int m  = q & 31;
            int v  = __ldg(idx32 + ((size_t)(node0 + nl) * MM + m) * stride);
            s_idx[nl * PI4 + m] = ((unsigned)v < (unsigned)NN) ? v : 0;
        }
    }

    // --- stage weights [nl][d][m]: 384 float4, coalesced ---
    {
        const float4* wsrc = (const float4*)(w + (size_t)node0 * (DD * MM));
#pragma unroll
        for (int p = 0; p < 2; p++) {
            int q = threadIdx.x + p * 256;            // float4 slot
            if (q < 384) {
                float4 v = __ldg(wsrc + q);
                int nl = q / 24;
                int r  = q - nl * 24;                 // d*8 + m4
                int dq = r >> 3;
                int m4 = r & 7;
                *(float4*)(s_w + nl * PN4 + dq * PD4 + m4 * 4) = v;
            }
        }
    }

    __syncthreads();

    const int dl = l >> 2;                            // 0..3 (3 = zero pad)
    const float* wl = s_w + nodeL * PN4 + ((dl < 3) ? dl : 2) * PD4;
    const int*   il = s_idx + nodeL * PI4;
    const unsigned* fb = (const unsigned*)g_fsth + l; // + ridx*16 per gather

    float acc0 = 0.f, acc1 = 0.f;

#pragma unroll
    for (int mo = 0; mo < 8; mo++) {
        int4   i4 = *(const int4*)(il + 4 * mo);      // idx m=4mo..4mo+3 (bcast)
        float4 wv = *(const float4*)(wl + 4 * mo);    // this lane's d weights

#pragma unroll
        for (int mi = 0; mi < 4; mi++) {
            int   ridx = (mi == 0) ? i4.x : (mi == 1) ? i4.y : (mi == 2) ? i4.z : i4.w;
            float wm   = (mi == 0) ? wv.x : (mi == 1) ? wv.y : (mi == 2) ? wv.z : wv.w;
            unsigned pw = __ldg(fb + (size_t)ridx * 16);   // 4B of 64B row
            float2 ff = __half22float2(*reinterpret_cast<__half2*>(&pw));
            acc0 += wm * ff.x;                        // batch 2*(l&3)
            acc1 += wm * ff.y;                        // batch 2*(l&3)+1
        }
    }

    // --- reduce over d: width-16 butterfly (d=3 lanes carry exact zeros) ---
    acc0 += __shfl_xor_sync(FULL, acc0, 4, 16);
    acc1 += __shfl_xor_sync(FULL, acc1, 4, 16);
    acc0 += __shfl_xor_sync(FULL, acc0, 8, 16);
    acc1 += __shfl_xor_sync(FULL, acc1, 8, 16);

    if (l < 4) {                                      // batch pair l
        s_out[(2 * l) * PO4 + nodeL]     = acc0;
        s_out[(2 * l + 1) * PO4 + nodeL] = acc1;
    }

    __syncthreads();

    // --- coalesced output: 128 values, threads 0-127 ---
    if (threadIdx.x < 128) {
        int b  = threadIdx.x >> 4;                    // batch
        int n2 = threadIdx.x & 15;                    // local node
        out[(size_t)b * NN + node0 + n2] = s_out[b * PO4 + n2];
    }
}

// ---------------------------------------------------------------------------
// Launch. Inputs resolved BY SIZE (element counts distinct):
//   fs = 2,400,000   weights = 9,600,000   idx = 3,200,000
// ---------------------------------------------------------------------------
extern "C" void kernel_launch(void* const* d_in, const int* in_sizes, int n_in,
                              void* d_out, int out_size) {
    const float* fs  = nullptr;
    const float* w   = nullptr;
    const int*   idx = nullptr;

    for (int i = 0; i < n_in; i++) {
        if (in_sizes[i] == BB * NN * DD)      fs  = (const float*)d_in[i];
        else if (in_sizes[i] == NN * DD * MM) w   = (const float*)d_in[i];
        else if (in_sizes[i] == NN * MM)      idx = (const int*)d_in[i];
    }
    if (!fs)  fs  = (const float*)d_in[0];
    if (!w)   w   = (const float*)d_in[1];
    if (!idx) idx = (const int*)d_in[2];

    float* out = (float*)d_out;

    int t_threads = NN * DD;
    transpose_fs_kernel<<<(t_threads + 255) / 256, 256>>>(fs, idx);

    rbffd_main_kernel<<<NN / 16, 256>>>(w, idx, out);   // 6250 blocks
}

// round 16
// speedup vs baseline: 1.4018x; 1.0804x over previous
#include <cuda_runtime.h>
#include <cuda_fp16.h>

#define NN 100000
#define MM 32
#define DD 3
#define BB 8

// fs transposed to [n][d][b] fp16: row n = 8 uint2 slots (64 B, aligned).
// slot (2d + half) = 4 batches of fp16; slots 6,7 = explicit zeros.
__device__ __align__(128) uint2 g_fsth[NN * 8];

// 1 if stencil buffer is int64, 0 if int32 (jax x64-disabled downgrade).
__device__ int g_idx_is64;

// ---------------------------------------------------------------------------
// Kernel 1: transpose+compress fs (B,N,D) f32 -> [n][d][b] fp16 rows.
// Thread 0 also detects idx dtype. d==0 thread zeroes pad slots 6,7.
// ---------------------------------------------------------------------------
__global__ void __launch_bounds__(256) transpose_fs_kernel(
    const float* __restrict__ fs, const int* __restrict__ idx32)
{
    int t = blockIdx.x * 256 + threadIdx.x;   // t = n*3 + d
    if (t == 0) {
        int all_zero = 1;
#pragma unroll
        for (int k = 0; k < 64; k++)
            if (idx32[2 * k + 1] != 0) { all_zero = 0; break; }
        g_idx_is64 = all_zero;
    }
    if (t >= NN * DD) return;
    float v[BB];
#pragma unroll
    for (int b = 0; b < BB; b++) v[b] = __ldg(fs + (size_t)b * (NN * DD) + t);
    int n = t / DD;
    int d = t - n * DD;

    __half2 a01 = __floats2half2_rn(v[0], v[1]);
    __half2 a23 = __floats2half2_rn(v[2], v[3]);
    __half2 a45 = __floats2half2_rn(v[4], v[5]);
    __half2 a67 = __floats2half2_rn(v[6], v[7]);
    uint2 u0, u1;
    u0.x = *reinterpret_cast<unsigned int*>(&a01);
    u0.y = *reinterpret_cast<unsigned int*>(&a23);
    u1.x = *reinterpret_cast<unsigned int*>(&a45);
    u1.y = *reinterpret_cast<unsigned int*>(&a67);
    g_fsth[(size_t)n * 8 + d * 2]     = u0;   // d, batches 0-3
    g_fsth[(size_t)n * 8 + d * 2 + 1] = u1;   // d, batches 4-7
    if (d == 0) {
        uint2 z = make_uint2(0u, 0u);
        g_fsth[(size_t)n * 8 + 6] = z;        // zero pads (lanes 6,7 read these)
        g_fsth[(size_t)n * 8 + 7] = z;
    }
}

// ---------------------------------------------------------------------------
// Kernel 2: gather + contraction (R11 core + PDL prologue overlap).
// Block = 256 threads = 32 nodes (8 lanes/node, 4 nodes/warp).
// Phase A (independent of prepass): stage weights into smem.
// cudaGridDependencySynchronize() -> Phase B: stage idx, then gather.
// Per m: one LDG.64 covers 4 nodes' rows; lane j: d=j>>1, batch-half=j&1;
// lanes 6,7 read the zero pad slots (same line, exact zeros).
// ---------------------------------------------------------------------------
#define PN 116   // s_w words per node   (116 mod 32 = 20)
#define PD 36    // s_w words per d-row  ( 36 mod 32 =  4)
#define PI 36    // s_idx words per node ( 36 mod 32 =  4)
#define PO 36    // s_out node stride

__global__ void __launch_bounds__(256, 8) rbffd_main_kernel(
    const float* __restrict__ w,        // (N, D, M) f32
    const int* __restrict__ idx32,      // (N, M) int32 or int64 pairs
    float* __restrict__ out)            // (B, N) f32
{
    const unsigned FULL = 0xffffffffu;
    __shared__ __align__(16) float s_w[32 * PN];      // 14848 B
    __shared__ __align__(16) int   s_idx[32 * PI];    //  4608 B
    __shared__ float s_out[BB * PO];                  //  1152 B

    const int node0 = blockIdx.x * 32;
    const int nodeL = threadIdx.x >> 3;               // 0..31 local node
    const int node  = node0 + nodeL;
    const int j     = threadIdx.x & 7;                // lane in node group

    // --- Phase A: stage weights [nl][d][m] (no prepass dependency) ---
    {
        const float4* wsrc = (const float4*)(w + (size_t)node0 * (DD * MM));
#pragma unroll
        for (int p = 0; p < 3; p++) {
            int q = threadIdx.x + p * 256;            // float4 index 0..767
            float4 v = __ldcs(wsrc + q);              // streamed, evict-first
            int nl = q / 24;
            int r  = q % 24;
            int dq = r >> 3;
            int m4 = r & 7;
            *(float4*)(s_w + nl * PN + dq * PD + m4 * 4) = v;
        }
    }

    // --- wait for prepass grid (PDL edge) before touching its outputs ---
    cudaGridDependencySynchronize();

    // --- Phase B: stage this lane's 4 stencil indices (m = 4j..4j+3) ---
    {
        int4 ci;
        if (g_idx_is64) {
            const int* irow = idx32 + (size_t)node * MM * 2;
            ci.x = __ldg(irow + (4 * j + 0) * 2);
            ci.y = __ldg(irow + (4 * j + 1) * 2);
            ci.z = __ldg(irow + (4 * j + 2) * 2);
            ci.w = __ldg(irow + (4 * j + 3) * 2);
        } else {
            ci = __ldg((const int4*)(idx32 + (size_t)node * MM + 4 * j));
        }
        ci.x = ((unsigned)ci.x < (unsigned)NN) ? ci.x : 0;
        ci.y = ((unsigned)ci.y < (unsigned)NN) ? ci.y : 0;
        ci.z = ((unsigned)ci.z < (unsigned)NN) ? ci.z : 0;
        ci.w = ((unsigned)ci.w < (unsigned)NN) ? ci.w : 0;
        *(int4*)(s_idx + nodeL * PI + 4 * j) = ci;
    }

    __syncthreads();

    const int dj = (j < 6) ? (j >> 1) : 2;
    const float* wl = s_w + nodeL * PN + dj * PD;
    const int*   il = s_idx + nodeL * PI;
    const uint2* fb = g_fsth + j;                     // + ridx*8 per gather

    float4 acc = make_float4(0.f, 0.f, 0.f, 0.f);

#pragma unroll
    for (int half = 0; half < 2; half++) {
#pragma unroll
        for (int mo = 0; mo < 4; mo++) {
            const int mq = half * 4 + mo;
            int4   i4 = *(const int4*)(il + 4 * mq);
            float4 wv = *(const float4*)(wl + 4 * mq);

#pragma unroll
            for (int mi = 0; mi < 4; mi++) {
                int   ridx = (mi == 0) ? i4.x : (mi == 1) ? i4.y : (mi == 2) ? i4.z : i4.w;
                float wm   = (mi == 0) ? wv.x : (mi == 1) ? wv.y : (mi == 2) ? wv.z : wv.w;
                uint2 p = __ldg(fb + (size_t)ridx * 8);
                __half2 h0 = *reinterpret_cast<__half2*>(&p.x);
                __half2 h1 = *reinterpret_cast<__half2*>(&p.y);
                float2 f0 = __half22float2(h0);
                float2 f1 = __half22float2(h1);
                acc.x += wm * f0.x;
                acc.y += wm * f0.y;
                acc.z += wm * f1.x;
                acc.w += wm * f1.y;
            }
        }
    }

    // --- reduce over d within the group (lanes 6,7 carry exact zeros) ---
    {
        float a[4] = {acc.x, acc.y, acc.z, acc.w};
#pragma unroll
        for (int c = 0; c < 4; c++) a[c] += __shfl_xor_sync(FULL, a[c], 2, 8);
#pragma unroll
        for (int c = 0; c < 4; c++) a[c] += __shfl_xor_sync(FULL, a[c], 4, 8);
        if (j < 2) {                                  // j=0: b0-3, j=1: b4-7
#pragma unroll
            for (int c = 0; c < 4; c++)
                s_out[(4 * j + c) * PO + nodeL] = a[c];
        }
    }

    __syncthreads();

    // --- coalesced output: warp b writes out[b][node0 .. node0+31] ---
    {
        int b    = threadIdx.x >> 5;                  // 0..7
        int lane = threadIdx.x & 31;
        out[(size_t)b * NN + node0 + lane] = s_out[b * PO + lane];
    }
}

// ---------------------------------------------------------------------------
// Launch. Inputs resolved BY SIZE (element counts distinct):
//   fs = 2,400,000   weights = 9,600,000   idx = 3,200,000
// Main kernel launched with Programmatic Stream Serialization (PDL) so its
// weight-staging prologue overlaps the transpose prepass.
// ---------------------------------------------------------------------------
extern "C" void kernel_launch(void* const* d_in, const int* in_sizes, int n_in,
                              void* d_out, int out_size) {
    const float* fs  = nullptr;
    const float* w   = nullptr;
    const int*   idx = nullptr;

    for (int i = 0; i < n_in; i++) {
        if (in_sizes[i] == BB * NN * DD)      fs  = (const float*)d_in[i];
        else if (in_sizes[i] == NN * DD * MM) w   = (const float*)d_in[i];
        else if (in_sizes[i] == NN * MM)      idx = (const int*)d_in[i];
    }
    if (!fs)  fs  = (const float*)d_in[0];
    if (!w)   w   = (const float*)d_in[1];
    if (!idx) idx = (const int*)d_in[2];

    float* out = (float*)d_out;

    int t_threads = NN * DD;
    transpose_fs_kernel<<<(t_threads + 255) / 256, 256>>>(fs, idx);

    cudaLaunchConfig_t cfg = {};
    cfg.gridDim  = dim3(NN / 32, 1, 1);               // 3125 blocks
    cfg.blockDim = dim3(256, 1, 1);
    cfg.dynamicSmemBytes = 0;
    cfg.stream = 0;                                   // same (capture) stream
    cudaLaunchAttribute attrs[1];
    attrs[0].id = cudaLaunchAttributeProgrammaticStreamSerialization;
    attrs[0].val.programmaticStreamSerializationAllowed = 1;
    cfg.attrs = attrs;
    cfg.numAttrs = 1;
    cudaLaunchKernelEx(&cfg, rbffd_main_kernel, w, idx, out);
}